// round 1
// baseline (speedup 1.0000x reference)
#include <cuda_runtime.h>
#include <math.h>

#define N_NODES 50000
#define N_EDGES 800000
#define SCAN_B  1024
#define SCAN_NB ((N_NODES + SCAN_B - 1) / SCAN_B)   // 49

// ---------------- scratch (static device memory; no allocs) ----------------
__device__ int   g_counts[N_NODES];
__device__ int   g_rowptr[N_NODES + 1];
__device__ int   g_cursor[N_NODES];
__device__ int   g_tmp[N_NODES];
__device__ int   g_bsum[64];
__device__ int   g_boff[64];
__device__ int   g_esrc[N_EDGES];
__device__ float g_ewt[N_EDGES];
__device__ float g_h[2][N_NODES * 64];
__device__ float g_aggr[N_NODES * 64];
__device__ float g_t[N_NODES];
__device__ float g_r[N_NODES];

// ---------------- CSR build ----------------
__global__ void k_zero_counts() {
    int i = blockIdx.x * blockDim.x + threadIdx.x;
    if (i < N_NODES) g_counts[i] = 0;
}

__global__ void k_hist(const int* __restrict__ dst) {
    int e = blockIdx.x * blockDim.x + threadIdx.x;
    if (e < N_EDGES) atomicAdd(&g_counts[dst[e]], 1);
}

__global__ void k_scan_part() {
    __shared__ int s[SCAN_B];
    int tid = threadIdx.x;
    int i = blockIdx.x * SCAN_B + tid;
    int v = (i < N_NODES) ? g_counts[i] : 0;
    s[tid] = v;
    __syncthreads();
    for (int off = 1; off < SCAN_B; off <<= 1) {
        int t = (tid >= off) ? s[tid - off] : 0;
        __syncthreads();
        s[tid] += t;
        __syncthreads();
    }
    if (i < N_NODES) g_tmp[i] = s[tid];
    if (tid == SCAN_B - 1) g_bsum[blockIdx.x] = s[tid];
}

__global__ void k_scan_sums() {
    __shared__ int s[64];
    int tid = threadIdx.x;
    int v = (tid < SCAN_NB) ? g_bsum[tid] : 0;
    s[tid] = v;
    __syncthreads();
    for (int off = 1; off < 64; off <<= 1) {
        int t = (tid >= off) ? s[tid - off] : 0;
        __syncthreads();
        s[tid] += t;
        __syncthreads();
    }
    if (tid < SCAN_NB) g_boff[tid] = s[tid] - v;  // exclusive
}

__global__ void k_scan_fin() {
    int i = blockIdx.x * SCAN_B + threadIdx.x;
    if (i < N_NODES) {
        int incl = g_tmp[i] + g_boff[blockIdx.x];
        int excl = incl - g_counts[i];
        g_rowptr[i] = excl;
        g_cursor[i] = excl;
        if (i == N_NODES - 1) g_rowptr[N_NODES] = incl;
    }
}

__global__ void k_scatter(const int* __restrict__ src, const int* __restrict__ dst,
                          const float* __restrict__ ew) {
    int e = blockIdx.x * blockDim.x + threadIdx.x;
    if (e < N_EDGES) {
        int d = dst[e];
        int p = atomicAdd(&g_cursor[d], 1);
        g_esrc[p] = src[e];
        g_ewt[p]  = ew[e];
    }
}

// ---------------- aggregation (pull-based, warp per node) ----------------
__global__ void k_aggr64(int sel) {
    int gw  = (blockIdx.x * blockDim.x + threadIdx.x) >> 5;
    int lane = threadIdx.x & 31;
    if (gw >= N_NODES) return;
    const float* __restrict__ h = g_h[sel];
    int start = g_rowptr[gw], end = g_rowptr[gw + 1];
    float a0 = 0.f, a1 = 0.f;
    for (int base = start; base < end; base += 32) {
        int e = base + lane;
        int s = 0; float w = 0.f;
        if (e < end) { s = g_esrc[e]; w = g_ewt[e]; }
        int cnt = min(32, end - base);
        for (int j = 0; j < cnt; j++) {
            int   sj = __shfl_sync(0xffffffffu, s, j);
            float wj = __shfl_sync(0xffffffffu, w, j);
            a0 += wj * __ldg(&h[sj * 64 + lane]);
            a1 += wj * __ldg(&h[sj * 64 + 32 + lane]);
        }
    }
    g_aggr[gw * 64 + lane]      = a0;
    g_aggr[gw * 64 + 32 + lane] = a1;
}

__global__ void k_aggr13(const float* __restrict__ x) {
    int gw  = (blockIdx.x * blockDim.x + threadIdx.x) >> 5;
    int lane = threadIdx.x & 31;
    if (gw >= N_NODES) return;
    int start = g_rowptr[gw], end = g_rowptr[gw + 1];
    float a0 = 0.f;
    for (int base = start; base < end; base += 32) {
        int e = base + lane;
        int s = 0; float w = 0.f;
        if (e < end) { s = g_esrc[e]; w = g_ewt[e]; }
        int cnt = min(32, end - base);
        for (int j = 0; j < cnt; j++) {
            int   sj = __shfl_sync(0xffffffffu, s, j);
            float wj = __shfl_sync(0xffffffffu, w, j);
            if (lane < 13) a0 += wj * __ldg(&x[sj * 13 + lane]);
        }
    }
    if (lane < 13) g_aggr[gw * 13 + lane] = a0;
}

// ---------------- fused dual-GEMM: out = relu(aggr@Wrel + b + h@Wroot) ------
// 64 nodes per block, 256 threads; each thread: 1 node x 16 contiguous cols.
// W (both halves) staged in shared (broadcast-friendly reads).
template <int DIN, bool RELU>
__global__ void k_gemm(const float* __restrict__ Wrel, const float* __restrict__ brel,
                       const float* __restrict__ Wroot,
                       const float* __restrict__ xext,  // layer0 root input; else unused
                       int insel, int outsel) {
    __shared__ __align__(16) float sW[2 * DIN * 64];
    __shared__ float sb[64];
    int tid = threadIdx.x;
    for (int idx = tid; idx < DIN * 64; idx += 256) {
        sW[idx]            = Wrel[idx];
        sW[DIN * 64 + idx] = Wroot[idx];
    }
    if (tid < 64) sb[tid] = brel[tid];
    __syncthreads();

    int node = blockIdx.x * 64 + (tid >> 2);
    int c0   = (tid & 3) * 16;
    if (node >= N_NODES) return;

    float acc[16];
#pragma unroll
    for (int j = 0; j < 16; j++) acc[j] = sb[c0 + j];

    const float4* sW4 = (const float4*)sW;
    const float* arow = g_aggr + (long)node * DIN;
    const float* hrow = (DIN == 13) ? (xext + (long)node * 13)
                                    : (g_h[insel] + (long)node * 64);

    if (DIN == 64) {
        const float4* a4p = (const float4*)arow;
        const float4* h4p = (const float4*)hrow;
#pragma unroll 4
        for (int k4 = 0; k4 < 16; k4++) {
            float4 a4 = __ldg(a4p + k4);
            float av[4] = {a4.x, a4.y, a4.z, a4.w};
#pragma unroll
            for (int kk = 0; kk < 4; kk++) {
                int row = k4 * 4 + kk;
#pragma unroll
                for (int j = 0; j < 4; j++) {
                    float4 w = sW4[row * 16 + (c0 >> 2) + j];
                    acc[4 * j + 0] += av[kk] * w.x;
                    acc[4 * j + 1] += av[kk] * w.y;
                    acc[4 * j + 2] += av[kk] * w.z;
                    acc[4 * j + 3] += av[kk] * w.w;
                }
            }
        }
#pragma unroll 4
        for (int k4 = 0; k4 < 16; k4++) {
            float4 a4 = __ldg(h4p + k4);
            float av[4] = {a4.x, a4.y, a4.z, a4.w};
#pragma unroll
            for (int kk = 0; kk < 4; kk++) {
                int row = 64 + k4 * 4 + kk;
#pragma unroll
                for (int j = 0; j < 4; j++) {
                    float4 w = sW4[row * 16 + (c0 >> 2) + j];
                    acc[4 * j + 0] += av[kk] * w.x;
                    acc[4 * j + 1] += av[kk] * w.y;
                    acc[4 * j + 2] += av[kk] * w.z;
                    acc[4 * j + 3] += av[kk] * w.w;
                }
            }
        }
    } else {
#pragma unroll
        for (int k = 0; k < DIN; k++) {
            float ak = __ldg(&arow[k]);
#pragma unroll
            for (int j = 0; j < 4; j++) {
                float4 w = sW4[k * 16 + (c0 >> 2) + j];
                acc[4 * j + 0] += ak * w.x;
                acc[4 * j + 1] += ak * w.y;
                acc[4 * j + 2] += ak * w.z;
                acc[4 * j + 3] += ak * w.w;
            }
        }
#pragma unroll
        for (int k = 0; k < DIN; k++) {
            float hk = __ldg(&hrow[k]);
#pragma unroll
            for (int j = 0; j < 4; j++) {
                float4 w = sW4[(DIN + k) * 16 + (c0 >> 2) + j];
                acc[4 * j + 0] += hk * w.x;
                acc[4 * j + 1] += hk * w.y;
                acc[4 * j + 2] += hk * w.z;
                acc[4 * j + 3] += hk * w.w;
            }
        }
    }

    float* outp = g_h[outsel] + (long)node * 64 + c0;
    float4* o4 = (float4*)outp;
#pragma unroll
    for (int j = 0; j < 4; j++) {
        float4 v;
        v.x = acc[4 * j + 0]; v.y = acc[4 * j + 1];
        v.z = acc[4 * j + 2]; v.w = acc[4 * j + 3];
        if (RELU) {
            v.x = fmaxf(v.x, 0.f); v.y = fmaxf(v.y, 0.f);
            v.z = fmaxf(v.z, 0.f); v.w = fmaxf(v.w, 0.f);
        }
        o4[j] = v;
    }
}

// ---------------- final layer (d_out = 1): project then scalar aggregate ----
__global__ void k_proj(int sel, const float* __restrict__ Wrel4,
                       const float* __restrict__ b4,
                       const float* __restrict__ Wroot4) {
    int gw  = (blockIdx.x * blockDim.x + threadIdx.x) >> 5;
    int lane = threadIdx.x & 31;
    if (gw >= N_NODES) return;
    const float* __restrict__ h = g_h[sel];
    float h0 = h[gw * 64 + lane];
    float h1 = h[gw * 64 + 32 + lane];
    float tt = h0 * __ldg(&Wrel4[lane])  + h1 * __ldg(&Wrel4[lane + 32]);
    float rr = h0 * __ldg(&Wroot4[lane]) + h1 * __ldg(&Wroot4[lane + 32]);
#pragma unroll
    for (int o = 16; o > 0; o >>= 1) {
        tt += __shfl_xor_sync(0xffffffffu, tt, o);
        rr += __shfl_xor_sync(0xffffffffu, rr, o);
    }
    if (lane == 0) {
        g_t[gw] = tt;
        g_r[gw] = rr + __ldg(&b4[0]);
    }
}

__global__ void k_final(float* __restrict__ out) {
    int gw  = (blockIdx.x * blockDim.x + threadIdx.x) >> 5;
    int lane = threadIdx.x & 31;
    if (gw >= N_NODES) return;
    int start = g_rowptr[gw], end = g_rowptr[gw + 1];
    float acc = 0.f;
    for (int e = start + lane; e < end; e += 32)
        acc += g_ewt[e] * __ldg(&g_t[g_esrc[e]]);
#pragma unroll
    for (int o = 16; o > 0; o >>= 1)
        acc += __shfl_xor_sync(0xffffffffu, acc, o);
    if (lane == 0) {
        float z = acc + g_r[gw];
        out[gw] = 1.f / (1.f + expf(-z));
    }
}

// ---------------- launch ----------------
extern "C" void kernel_launch(void* const* d_in, const int* in_sizes, int n_in,
                              void* d_out, int out_size) {
    const float* x  = (const float*)d_in[0];
    const int*   ei = (const int*)d_in[1];
    const float* ew = (const float*)d_in[2];
    const int* src = ei;
    const int* dst = ei + N_EDGES;

    const float* Wrel[5], * brel[5], * Wroot[5];
    for (int l = 0; l < 5; l++) {
        Wrel[l]  = (const float*)d_in[3 + 3 * l];
        brel[l]  = (const float*)d_in[4 + 3 * l];
        Wroot[l] = (const float*)d_in[5 + 3 * l];
    }
    float* out = (float*)d_out;

    const int TB = 256;
    int gN = (N_NODES + TB - 1) / TB;
    int gE = (N_EDGES + TB - 1) / TB;
    int gW = (N_NODES * 32 + TB - 1) / TB;   // warp-per-node grids
    int gG = (N_NODES + 63) / 64;            // gemm grids

    // CSR build (per launch; deterministic work)
    k_zero_counts<<<gN, TB>>>();
    k_hist<<<gE, TB>>>(dst);
    k_scan_part<<<SCAN_NB, SCAN_B>>>();
    k_scan_sums<<<1, 64>>>();
    k_scan_fin<<<SCAN_NB, SCAN_B>>>();
    k_scatter<<<gE, TB>>>(src, dst, ew);

    // layer 0: 13 -> 64 (aggregate in 13-dim)
    k_aggr13<<<gW, TB>>>(x);
    k_gemm<13, true><<<gG, TB>>>(Wrel[0], brel[0], Wroot[0], x, 0, 0);

    // layers 1-3: 64 -> 64
    k_aggr64<<<gW, TB>>>(0);
    k_gemm<64, true><<<gG, TB>>>(Wrel[1], brel[1], Wroot[1], nullptr, 0, 1);
    k_aggr64<<<gW, TB>>>(1);
    k_gemm<64, true><<<gG, TB>>>(Wrel[2], brel[2], Wroot[2], nullptr, 1, 0);
    k_aggr64<<<gW, TB>>>(0);
    k_gemm<64, true><<<gG, TB>>>(Wrel[3], brel[3], Wroot[3], nullptr, 0, 1);

    // layer 4: 64 -> 1, project first (aggregation commutes with linear map)
    k_proj<<<gW, TB>>>(1, Wrel[4], brel[4], Wroot[4]);
    k_final<<<gW, TB>>>(out);
}